// round 4
// baseline (speedup 1.0000x reference)
#include <cuda_runtime.h>
#include <cuda_bf16.h>

// Problem constants
#define B_    2
#define H_    16
#define S_    2048
#define D_    64
#define DM    1024
#define MTOT  4096   // B_*S_

static const long OUT_ELEMS  = (long)MTOT * DM;            // 4,194,304
static const long ATTN_ELEMS = (long)B_ * H_ * S_ * S_;    // 134,217,728

// Scratch (device-global; no runtime allocation allowed)
__device__ float g_q[B_*H_*S_*D_];
__device__ float g_k[B_*H_*S_*D_];
__device__ float g_v[B_*H_*S_*D_];
__device__ float g_ctx[MTOT*DM];
__device__ float g_attn[(size_t)B_*H_*S_*S_];

// ---------------------------------------------------------------------------
// tf32 helpers
// ---------------------------------------------------------------------------
__device__ __forceinline__ float tf(float f) {
    unsigned u;
    asm("cvt.rna.tf32.f32 %0, %1;" : "=r"(u) : "f"(f));
    return __uint_as_float(u);
}

__device__ __forceinline__ void mma_tf32(
    float& c0, float& c1, float& c2, float& c3,
    unsigned a0, unsigned a1, unsigned a2, unsigned a3,
    unsigned b0, unsigned b1)
{
    asm volatile(
        "mma.sync.aligned.m16n8k8.row.col.f32.tf32.tf32.f32 "
        "{%0,%1,%2,%3},{%4,%5,%6,%7},{%8,%9},{%0,%1,%2,%3};"
        : "+f"(c0), "+f"(c1), "+f"(c2), "+f"(c3)
        : "r"(a0), "r"(a1), "r"(a2), "r"(a3), "r"(b0), "r"(b1));
}

// Interleaved A/K layouts: [chunk][row][8]; pos 2j <-> k=8ch+j, 2j+1 <-> k=8ch+j+4
#define CSA  1026   // 128-row chunk stride
#define CSA2 514    // 64-row chunk stride
// Dense-gemm W layout
#define RSB 132
#define CSB 1056
// V tile (d=64) layout: [chunk][kk][68]
#define RSV 68
#define CSV 548

// interleaved STS of 8 consecutive k values (two float4) with tf32 convert
__device__ __forceinline__ void sts_pair8(float* d, float4 lo, float4 hi) {
    float a0[4] = {lo.x, lo.y, lo.z, lo.w};
    float a1[4] = {hi.x, hi.y, hi.z, hi.w};
    #pragma unroll
    for (int j = 0; j < 4; j++) {
        float2 t; t.x = tf(a0[j]); t.y = tf(a1[j]);
        *(float2*)(d + 2 * j) = t;
    }
}

// ---------------------------------------------------------------------------
// K1/K5: C[4096,1024] = A[4096,1024] @ W[1024,1024] + bias   (tf32 MMA)
// ---------------------------------------------------------------------------
template<int SPLIT>
__global__ __launch_bounds__(256)
void gemm_tc(const float* __restrict__ A, const float* __restrict__ W,
             const float* __restrict__ bias, float* __restrict__ C)
{
    extern __shared__ float sm[];
    float* As = sm;           // 2 bufs * 4*CSA = 8208
    float* Bs = sm + 8208;    // 2 bufs * 4*CSB = 8448

    const int tid = threadIdx.x, lane = tid & 31, warp = tid >> 5;
    const int wm = warp >> 2, wn = warp & 3;
    const int bx = blockIdx.x, by = blockIdx.y;
    const float* Ab = A + (long)by * 128 * DM;
    const float* Wb = W + (long)bx * 128;

    const int a_ch = tid & 3, a_m = tid >> 2;
    const int b_cg = tid & 31, b_k = tid >> 5;

    float acc[4][4][4];
    #pragma unroll
    for (int i = 0; i < 4; i++)
        #pragma unroll
        for (int j = 0; j < 4; j++)
            #pragma unroll
            for (int q = 0; q < 4; q++) acc[i][j][q] = 0.f;

    float4 ar[2][2], br[4];
    const int b_kk = 2 * (b_k & 3) + ((b_k >> 2) & 1);

    #pragma unroll
    for (int p = 0; p < 2; p++) {
        const float* s = Ab + (long)(a_m + 64 * p) * DM + a_ch * 8;
        ar[p][0] = *(const float4*)s;
        ar[p][1] = *(const float4*)(s + 4);
    }
    #pragma unroll
    for (int p = 0; p < 4; p++)
        br[p] = *(const float4*)(Wb + (long)(b_k + 8 * p) * DM + b_cg * 4);

    {
        #pragma unroll
        for (int p = 0; p < 2; p++)
            sts_pair8(As + a_ch * CSA + (a_m + 64 * p) * 8, ar[p][0], ar[p][1]);
        #pragma unroll
        for (int p = 0; p < 4; p++) {
            float* d = Bs + p * CSB + b_kk * RSB + b_cg * 4;
            float4 t;
            t.x = tf(br[p].x); t.y = tf(br[p].y); t.z = tf(br[p].z); t.w = tf(br[p].w);
            *(float4*)d = t;
        }
    }
    __syncthreads();

    const int NK = DM / 32;
    for (int it = 0; it < NK; ++it) {
        const bool pre = (it + 1 < NK);
        if (pre) {
            const int k0 = (it + 1) * 32;
            #pragma unroll
            for (int p = 0; p < 2; p++) {
                const float* s = Ab + (long)(a_m + 64 * p) * DM + k0 + a_ch * 8;
                ar[p][0] = *(const float4*)s;
                ar[p][1] = *(const float4*)(s + 4);
            }
            #pragma unroll
            for (int p = 0; p < 4; p++)
                br[p] = *(const float4*)(Wb + (long)(k0 + b_k + 8 * p) * DM + b_cg * 4);
        }

        const float* Ac = As + (it & 1) * 4104;
        const float* Bc = Bs + (it & 1) * 4224;
        #pragma unroll
        for (int ch = 0; ch < 4; ch++) {
            unsigned a[4][4], b[4][2];
            #pragma unroll
            for (int mi = 0; mi < 4; mi++) {
                int r = wm * 64 + mi * 16 + (lane >> 2);
                float2 lo = *(const float2*)(Ac + ch * CSA + r * 8 + 2 * (lane & 3));
                float2 hi = *(const float2*)(Ac + ch * CSA + (r + 8) * 8 + 2 * (lane & 3));
                a[mi][0] = __float_as_uint(lo.x); a[mi][1] = __float_as_uint(hi.x);
                a[mi][2] = __float_as_uint(lo.y); a[mi][3] = __float_as_uint(hi.y);
            }
            #pragma unroll
            for (int ni = 0; ni < 4; ni++) {
                int n = wn * 32 + ni * 8 + (lane >> 2);
                int c2 = 2 * (lane & 3);
                b[ni][0] = __float_as_uint(Bc[ch * CSB + c2 * RSB + n]);
                b[ni][1] = __float_as_uint(Bc[ch * CSB + (c2 + 1) * RSB + n]);
            }
            #pragma unroll
            for (int mi = 0; mi < 4; mi++)
                #pragma unroll
                for (int ni = 0; ni < 4; ni++)
                    mma_tf32(acc[mi][ni][0], acc[mi][ni][1], acc[mi][ni][2], acc[mi][ni][3],
                             a[mi][0], a[mi][1], a[mi][2], a[mi][3],
                             b[ni][0], b[ni][1]);
        }

        if (pre) {
            float* Ad = As + ((it + 1) & 1) * 4104;
            float* Bd = Bs + ((it + 1) & 1) * 4224;
            #pragma unroll
            for (int p = 0; p < 2; p++)
                sts_pair8(Ad + a_ch * CSA + (a_m + 64 * p) * 8, ar[p][0], ar[p][1]);
            #pragma unroll
            for (int p = 0; p < 4; p++) {
                float* d = Bd + p * CSB + b_kk * RSB + b_cg * 4;
                float4 t;
                t.x = tf(br[p].x); t.y = tf(br[p].y); t.z = tf(br[p].z); t.w = tf(br[p].w);
                *(float4*)d = t;
            }
            __syncthreads();
        }
    }

    #pragma unroll
    for (int mi = 0; mi < 4; mi++) {
        int r0 = by * 128 + wm * 64 + mi * 16 + (lane >> 2);
        #pragma unroll
        for (int ni = 0; ni < 4; ni++) {
            int n = bx * 128 + wn * 32 + ni * 8 + 2 * (lane & 3);
            float bz0 = bias[n], bz1 = bias[n + 1];
            float2 t0, t1;
            t0.x = acc[mi][ni][0] + bz0; t0.y = acc[mi][ni][1] + bz1;
            t1.x = acc[mi][ni][2] + bz0; t1.y = acc[mi][ni][3] + bz1;
            if (SPLIT) {
                int bb = r0 >> 11, s = r0 & 2047;
                int h = n >> 6, d = n & 63;
                long base = (((long)(bb * H_ + h)) * S_ + s) * D_ + d;
                *(float2*)(C + base) = t0;
                *(float2*)(C + base + 8 * D_) = t1;
            } else {
                *(float2*)(C + (long)r0 * DM + n) = t0;
                *(float2*)(C + (long)(r0 + 8) * DM + n) = t1;
            }
        }
    }
}

// ---------------------------------------------------------------------------
// Fused attention: per CTA 64 query rows of one (b,h).
// Phase 1: S = QK^T/8 + mask, accumulate sum(exp) per row (NO gmem writes).
// Phase 2: recompute S tile-by-tile (64 keys), p = exp(x)*inv, write attn,
//          stage p in smem, accumulate ctx = P@V. Single attn gmem write.
// Smem (floats): Qs 4112 | msk 2048 | invs 64 | red 256 | work 21104 = 27584
// work: phase1 K tiles 2x8208; phase2 K2 2x4112 @0, V 2x4384 @8224, P 4112 @16992
// ---------------------------------------------------------------------------
__global__ __launch_bounds__(256, 2)
void attn_fused_tc(const float* __restrict__ Qh, const float* __restrict__ Kh,
                   const float* __restrict__ Vh, const float* __restrict__ mask,
                   float* __restrict__ attn, float* __restrict__ ctx)
{
    extern __shared__ float sm[];
    float* Qs   = sm;            // 4112
    float* msk  = sm + 4112;     // 2048
    float* invs = sm + 6160;     // 64
    float* red  = sm + 6224;     // 256
    float* work = sm + 6480;     // 21104

    const int tid = threadIdx.x, lane = tid & 31, warp = tid >> 5;
    const int bh = blockIdx.z;
    const int row0 = blockIdx.x * 64;
    const float* Qb = Qh + ((long)bh * S_ + row0) * D_;
    const float* Kb = Kh + (long)bh * S_ * D_;
    const float* Vb = Vh + (long)bh * S_ * D_;
    float* attnb = attn + (long)bh * S_ * S_ + (long)row0 * S_;
    const int bb = bh >> 4;

    // mask -> smem
    #pragma unroll
    for (int i = tid; i < 512; i += 256)
        ((float4*)msk)[i] = ((const float4*)(mask + (long)bb * S_))[i];

    const int ch = tid & 7, m = tid >> 3;

    // Q (64 rows) -> smem, interleaved CSA2 layout
    #pragma unroll
    for (int p = 0; p < 2; p++) {
        int row = m + 32 * p;
        const float* sq = Qb + (long)row * D_ + ch * 8;
        sts_pair8(Qs + ch * CSA2 + row * 8, *(const float4*)sq, *(const float4*)(sq + 4));
    }
    // K tile 0 (128 keys) -> work buf0
    #pragma unroll
    for (int p = 0; p < 4; p++) {
        int row = m + 32 * p;
        const float* sk = Kb + (long)row * D_ + ch * 8;
        sts_pair8(work + ch * CSA + row * 8, *(const float4*)sk, *(const float4*)(sk + 4));
    }
    __syncthreads();

    // ============ Phase 1: row sums of exp ============
    const int wm1 = warp >> 2, wn1 = warp & 3;   // 2m x 4n, warp tile 32x32
    float ssum[4] = {0.f, 0.f, 0.f, 0.f};
    float4 kr[8];

    for (int kt = 0; kt < 16; ++kt) {
        const bool pre = (kt + 1 < 16);
        if (pre) {
            #pragma unroll
            for (int p = 0; p < 4; p++) {
                int row = (kt + 1) * 128 + m + 32 * p;
                const float* sk = Kb + (long)row * D_ + ch * 8;
                kr[2*p]   = *(const float4*)sk;
                kr[2*p+1] = *(const float4*)(sk + 4);
            }
        }

        float acc[2][4][4];
        #pragma unroll
        for (int i = 0; i < 2; i++)
            #pragma unroll
            for (int j = 0; j < 4; j++)
                #pragma unroll
                for (int q = 0; q < 4; q++) acc[i][j][q] = 0.f;

        const float* Kc = work + (kt & 1) * 8208;
        #pragma unroll
        for (int c = 0; c < 8; c++) {
            unsigned a[2][4], b[4][2];
            #pragma unroll
            for (int mi = 0; mi < 2; mi++) {
                int r = wm1 * 32 + mi * 16 + (lane >> 2);
                float2 lo = *(const float2*)(Qs + c * CSA2 + r * 8 + 2 * (lane & 3));
                float2 hi = *(const float2*)(Qs + c * CSA2 + (r + 8) * 8 + 2 * (lane & 3));
                a[mi][0] = __float_as_uint(lo.x); a[mi][1] = __float_as_uint(hi.x);
                a[mi][2] = __float_as_uint(lo.y); a[mi][3] = __float_as_uint(hi.y);
            }
            #pragma unroll
            for (int ni = 0; ni < 4; ni++) {
                int n = wn1 * 32 + ni * 8 + (lane >> 2);
                float2 v = *(const float2*)(Kc + c * CSA + n * 8 + 2 * (lane & 3));
                b[ni][0] = __float_as_uint(v.x);
                b[ni][1] = __float_as_uint(v.y);
            }
            #pragma unroll
            for (int mi = 0; mi < 2; mi++)
                #pragma unroll
                for (int ni = 0; ni < 4; ni++)
                    mma_tf32(acc[mi][ni][0], acc[mi][ni][1], acc[mi][ni][2], acc[mi][ni][3],
                             a[mi][0], a[mi][1], a[mi][2], a[mi][3],
                             b[ni][0], b[ni][1]);
        }

        // accumulate exp sums (mask applied)
        #pragma unroll
        for (int mi = 0; mi < 2; mi++) {
            #pragma unroll
            for (int ni = 0; ni < 4; ni++) {
                int n = kt * 128 + wn1 * 32 + ni * 8 + 2 * (lane & 3);
                float2 mm = *(const float2*)(msk + n);
                float x0 = fmaf(acc[mi][ni][0], 0.125f, -1e9f * mm.x);
                float x1 = fmaf(acc[mi][ni][1], 0.125f, -1e9f * mm.y);
                float x2 = fmaf(acc[mi][ni][2], 0.125f, -1e9f * mm.x);
                float x3 = fmaf(acc[mi][ni][3], 0.125f, -1e9f * mm.y);
                ssum[mi*2]   += __expf(x0) + __expf(x1);
                ssum[mi*2+1] += __expf(x2) + __expf(x3);
            }
        }

        if (pre) {
            float* Kd = work + ((kt + 1) & 1) * 8208;
            #pragma unroll
            for (int p = 0; p < 4; p++)
                sts_pair8(Kd + ch * CSA + (m + 32 * p) * 8, kr[2*p], kr[2*p+1]);
            __syncthreads();
        }
    }

    // ============ Phase 2 prologue LDGs (overlap with reduction) ============
    const int vcg = tid & 15, vkk = tid >> 4;
    float4 kr2[4], vr[4];
    #pragma unroll
    for (int p = 0; p < 2; p++) {
        const float* sk = Kb + (long)(m + 32 * p) * D_ + ch * 8;
        kr2[2*p]   = *(const float4*)sk;
        kr2[2*p+1] = *(const float4*)(sk + 4);
    }
    #pragma unroll
    for (int p = 0; p < 4; p++)
        vr[p] = *(const float4*)(Vb + (long)(vkk + 16 * p) * D_ + vcg * 4);

    // reduce sums -> invs
    #pragma unroll
    for (int i = 0; i < 4; i++) {
        ssum[i] += __shfl_xor_sync(0xFFFFFFFFu, ssum[i], 1);
        ssum[i] += __shfl_xor_sync(0xFFFFFFFFu, ssum[i], 2);
    }
    __syncthreads();   // phase1 K reads done before work reuse
    if ((lane & 3) == 0) {
        #pragma unroll
        for (int mi = 0; mi < 2; mi++)
            #pragma unroll
            for (int h = 0; h < 2; h++) {
                int r = wm1 * 32 + mi * 16 + (lane >> 2) + 8 * h;
                red[wn1 * 64 + r] = ssum[mi * 2 + h];
            }
    }
    __syncthreads();
    if (tid < 64)
        invs[tid] = 1.0f / (red[tid] + red[64 + tid] + red[128 + tid] + red[192 + tid]);

    // phase-2 smem regions
    float* K2 = work;            // buf * 4112
    float* Vs = work + 8224;     // buf * 4384
    float* Ps = work + 16992;    // 4112

    // STS tile 0
    #pragma unroll
    for (int p = 0; p < 2; p++)
        sts_pair8(K2 + ch * CSA2 + (m + 32 * p) * 8, kr2[2*p], kr2[2*p+1]);
    #pragma unroll
    for (int p = 0; p < 4; p++) {
        int key = vkk + 16 * p;
        int chv = key >> 3, kk = 2 * (key & 3) + ((key >> 2) & 1);
        float4 t;
        t.x = tf(vr[p].x); t.y = tf(vr[p].y); t.z = tf(vr[p].z); t.w = tf(vr[p].w);
        *(float4*)(Vs + chv * CSV + kk * RSV + vcg * 4) = t;
    }
    __syncthreads();

    // ============ Phase 2 main loop: 32 tiles of 64 keys ============
    const int wm = warp >> 1, wn = warp & 1;     // 4m x 2n, warp tile 16x32
    float acc_o[4][4];
    #pragma unroll
    for (int j = 0; j < 4; j++)
        #pragma unroll
        for (int q = 0; q < 4; q++) acc_o[j][q] = 0.f;

    const int r_w   = wm * 16 + (lane >> 2);
    const float iv0 = invs[r_w], iv1 = invs[r_w + 8];

    for (int kt = 0; kt < 32; ++kt) {
        const bool pre = (kt + 1 < 32);
        if (pre) {
            const int k0 = (kt + 1) * 64;
            #pragma unroll
            for (int p = 0; p < 2; p++) {
                const float* sk = Kb + (long)(k0 + m + 32 * p) * D_ + ch * 8;
                kr2[2*p]   = *(const float4*)sk;
                kr2[2*p+1] = *(const float4*)(sk + 4);
            }
            #pragma unroll
            for (int p = 0; p < 4; p++)
                vr[p] = *(const float4*)(Vb + (long)(k0 + vkk + 16 * p) * D_ + vcg * 4);
        }

        // --- recompute S (64x64) ---
        float acc_s[4][4];
        #pragma unroll
        for (int j = 0; j < 4; j++)
            #pragma unroll
            for (int q = 0; q < 4; q++) acc_s[j][q] = 0.f;

        const float* Kc = K2 + (kt & 1) * 4112;
        #pragma unroll
        for (int c = 0; c < 8; c++) {
            unsigned a[4], b[4][2];
            {
                float2 lo = *(const float2*)(Qs + c * CSA2 + r_w * 8 + 2 * (lane & 3));
                float2 hi = *(const float2*)(Qs + c * CSA2 + (r_w + 8) * 8 + 2 * (lane & 3));
                a[0] = __float_as_uint(lo.x); a[1] = __float_as_uint(hi.x);
                a[2] = __float_as_uint(lo.y); a[3] = __float_as_uint(hi.y);
            }
            #pragma unroll
            for (int ni = 0; ni < 4; ni++) {
                int n = wn * 32 + ni * 8 + (lane >> 2);
                float2 v = *(const float2*)(Kc + c * CSA2 + n * 8 + 2 * (lane & 3));
                b[ni][0] = __float_as_uint(v.x);
                b[ni][1] = __float_as_uint(v.y);
            }
            #pragma unroll
            for (int ni = 0; ni < 4; ni++)
                mma_tf32(acc_s[ni][0], acc_s[ni][1], acc_s[ni][2], acc_s[ni][3],
                         a[0], a[1], a[2], a[3], b[ni][0], b[ni][1]);
        }

        // --- epilogue: exp, write attn, stage P ---
        #pragma unroll
        for (int ni = 0; ni < 4; ni++) {
            int n_t = wn * 32 + ni * 8 + 2 * (lane & 3);
            int n_g = kt * 64 + n_t;
            float2 mm = *(const float2*)(msk + n_g);
            float x0 = fmaf(acc_s[ni][0], 0.125f, -1e9f * mm.x);
            float x1 = fmaf(acc_s[ni][1], 0.125f, -1e9f * mm.y);
            float x2 = fmaf(acc_s[ni][2], 0.125f, -1e9f * mm.x);
            float x3 = fmaf(acc_s[ni][3], 0.125f, -1e9f * mm.y);
            float e0 = __expf(x0) * iv0, e1 = __expf(x1) * iv0;
            float e2 = __expf(x2) * iv1, e3 = __expf(x3) * iv1;
            float2 t0; t0.x = e0; t0.y = e1;
            float2 t1; t1.x = e2; t1.y = e3;
            *(float2*)(attnb + (long)r_w * S_ + n_g) = t0;
            *(float2*)(attnb + (long)(r_w + 8) * S_ + n_g) = t1;
            // stage P (interleaved A layout)
            int chp = wn * 4 + ni;
            int kl0 = n_t & 7;            // even
            int pos0 = (kl0 < 4) ? 2 * kl0 : 2 * (kl0 - 4) + 1;
            int kl1 = kl0 + 1;
            int pos1 = (kl1 < 4) ? 2 * kl1 : 2 * (kl1 - 4) + 1;
            float* pb0 = Ps + chp * CSA2 + r_w * 8;
            float* pb1 = Ps + chp * CSA2 + (r_w + 8) * 8;
            pb0[pos0] = tf(e0); pb0[pos1] = tf(e1);
            pb1[pos0] = tf(e2); pb1[pos1] = tf(e3);
        }
        __syncthreads();

        // --- PV mma ---
        const float* Vc = Vs + (kt & 1) * 4384;
        #pragma unroll
        for (int c = 0; c < 8; c++) {
            unsigned a[4], b[4][2];
            {
                float2 lo = *(const float2*)(Ps + c * CSA2 + r_w * 8 + 2 * (lane & 3));
                float2 hi = *(const float2*)(Ps + c * CSA2 + (r_w + 8) * 8 + 2 * (lane & 3));
                a[0] = __float_as_uint(lo.x); a[1] = __float_as_uint(hi.x);
                a[2] = __float_as_uint(lo.y); a[3] = __float_as_uint(hi.y);
            }
            #pragma unroll
            for (int ni = 0; ni < 4; ni++) {
                int n = wn * 32 + ni * 8 + (lane >> 2);
                int c2 = 2 * (lane & 3);
                b[ni][0] = __float_as_uint(Vc[c * CSV + c2 * RSV + n]);
                b[ni][1] = __float_as_uint(Vc[c * CSV + (c2 + 1) * RSV + n]);
            }
            #pragma unroll
            for (int ni = 0; ni < 4; ni++)
                mma_tf32(acc_o[ni][0], acc_o[ni][1], acc_o[ni][2], acc_o[ni][3],
                         a[0], a[1], a[2], a[3], b[ni][0], b[ni][1]);
        }

        if (pre) {
            float* Kd = K2 + ((kt + 1) & 1) * 4112;
            float* Vd = Vs + ((kt + 1) & 1) * 4384;
            #pragma unroll
            for (int p = 0; p < 2; p++)
                sts_pair8(Kd + ch * CSA2 + (m + 32 * p) * 8, kr2[2*p], kr2[2*p+1]);
            #pragma unroll
            for (int p = 0; p < 4; p++) {
                int key = vkk + 16 * p;
                int chv = key >> 3, kk = 2 * (key & 3) + ((key >> 2) & 1);
                float4 t;
                t.x = tf(vr[p].x); t.y = tf(vr[p].y); t.z = tf(vr[p].z); t.w = tf(vr[p].w);
                *(float4*)(Vd + chv * CSV + kk * RSV + vcg * 4) = t;
            }
        }
        __syncthreads();
    }

    // epilogue: ctx merged-heads write
    const int h = bh & 15;
    #pragma unroll
    for (int ni = 0; ni < 4; ni++) {
        int s = row0 + r_w;
        int d = wn * 32 + ni * 8 + 2 * (lane & 3);
        long base = ((long)bb * S_ + s) * DM + h * 64 + d;
        float2 t0, t1;
        t0.x = acc_o[ni][0]; t0.y = acc_o[ni][1];
        t1.x = acc_o[ni][2]; t1.y = acc_o[ni][3];
        *(float2*)(ctx + base) = t0;
        *(float2*)(ctx + base + 8 * DM) = t1;
    }
}

// ---------------------------------------------------------------------------
extern "C" void kernel_launch(void* const* d_in, const int* in_sizes, int n_in,
                              void* d_out, int out_size) {
    const float* Q    = (const float*)d_in[0];
    const float* K    = (const float*)d_in[1];
    const float* V    = (const float*)d_in[2];
    const float* mask = (const float*)d_in[3];
    const float* Wq   = (const float*)d_in[4];
    const float* bq   = (const float*)d_in[5];
    const float* Wk   = (const float*)d_in[6];
    const float* bk   = (const float*)d_in[7];
    const float* Wv   = (const float*)d_in[8];
    const float* bv   = (const float*)d_in[9];
    const float* Wo   = (const float*)d_in[10];
    const float* bo   = (const float*)d_in[11];
    float* out = (float*)d_out;

    float *qp, *kp, *vp, *cp, *ap;
    cudaGetSymbolAddress((void**)&qp, g_q);
    cudaGetSymbolAddress((void**)&kp, g_k);
    cudaGetSymbolAddress((void**)&vp, g_v);
    cudaGetSymbolAddress((void**)&cp, g_ctx);
    cudaGetSymbolAddress((void**)&ap, g_attn);

    float* attn = ((long)out_size >= OUT_ELEMS + ATTN_ELEMS) ? (out + OUT_ELEMS) : ap;

    const int SM_GEMM = (8208 + 8448) * 4;    // 66624
    const int SM_ATT  = 27584 * 4;            // 110336
    cudaFuncSetAttribute(gemm_tc<0>, cudaFuncAttributeMaxDynamicSharedMemorySize, SM_GEMM);
    cudaFuncSetAttribute(gemm_tc<1>, cudaFuncAttributeMaxDynamicSharedMemorySize, SM_GEMM);
    cudaFuncSetAttribute(attn_fused_tc, cudaFuncAttributeMaxDynamicSharedMemorySize, SM_ATT);

    dim3 g1(DM / 128, MTOT / 128);
    gemm_tc<1><<<g1, 256, SM_GEMM>>>(Q, Wq, bq, qp);
    gemm_tc<1><<<g1, 256, SM_GEMM>>>(K, Wk, bk, kp);
    gemm_tc<1><<<g1, 256, SM_GEMM>>>(V, Wv, bv, vp);

    dim3 g2(S_ / 64, 1, B_ * H_);
    attn_fused_tc<<<g2, 256, SM_ATT>>>(qp, kp, vp, mask, attn, cp);

    gemm_tc<0><<<g1, 256, SM_GEMM>>>(cp, Wo, bo, out);
}

// round 5
// speedup vs baseline: 1.0969x; 1.0969x over previous
#include <cuda_runtime.h>
#include <cuda_bf16.h>

// Problem constants
#define B_    2
#define H_    16
#define S_    2048
#define D_    64
#define DM    1024
#define MTOT  4096   // B_*S_

static const long OUT_ELEMS  = (long)MTOT * DM;            // 4,194,304
static const long ATTN_ELEMS = (long)B_ * H_ * S_ * S_;    // 134,217,728

// Scratch (device-global; no runtime allocation allowed)
__device__ float g_q[B_*H_*S_*D_];
__device__ float g_k[B_*H_*S_*D_];
__device__ float g_v[B_*H_*S_*D_];
__device__ float g_ctx[MTOT*DM];
__device__ float g_attn[(size_t)B_*H_*S_*S_];
__device__ float g_inv[B_*H_*S_];   // per-row 1/sum(exp)

// ---------------------------------------------------------------------------
// tf32 helpers
// ---------------------------------------------------------------------------
__device__ __forceinline__ float tf(float f) {
    unsigned u;
    asm("cvt.rna.tf32.f32 %0, %1;" : "=r"(u) : "f"(f));
    return __uint_as_float(u);
}

__device__ __forceinline__ void mma_tf32(
    float& c0, float& c1, float& c2, float& c3,
    unsigned a0, unsigned a1, unsigned a2, unsigned a3,
    unsigned b0, unsigned b1)
{
    asm volatile(
        "mma.sync.aligned.m16n8k8.row.col.f32.tf32.tf32.f32 "
        "{%0,%1,%2,%3},{%4,%5,%6,%7},{%8,%9},{%0,%1,%2,%3};"
        : "+f"(c0), "+f"(c1), "+f"(c2), "+f"(c3)
        : "r"(a0), "r"(a1), "r"(a2), "r"(a3), "r"(b0), "r"(b1));
}

// Interleaved A/K layouts: [chunk][row][8]; pos 2j <-> k=8ch+j, 2j+1 <-> k=8ch+j+4
#define CSA  1026   // 128-row chunk stride
#define CSA2 514    // 64-row chunk stride
// Dense-gemm W layout
#define RSB 132
#define CSB 1056
// V tile (d=64) layout: [chunk][kk][68]
#define RSV 68
#define CSV 548

// interleaved STS of 8 consecutive k values (two float4) with tf32 convert
__device__ __forceinline__ void sts_pair8(float* d, float4 lo, float4 hi) {
    float a0[4] = {lo.x, lo.y, lo.z, lo.w};
    float a1[4] = {hi.x, hi.y, hi.z, hi.w};
    #pragma unroll
    for (int j = 0; j < 4; j++) {
        float2 t; t.x = tf(a0[j]); t.y = tf(a1[j]);
        *(float2*)(d + 2 * j) = t;
    }
}

// ---------------------------------------------------------------------------
// K1/K5: C[4096,1024] = A[4096,1024] @ W[1024,1024] + bias   (tf32 MMA)
// ---------------------------------------------------------------------------
template<int SPLIT>
__global__ __launch_bounds__(256)
void gemm_tc(const float* __restrict__ A, const float* __restrict__ W,
             const float* __restrict__ bias, float* __restrict__ C)
{
    extern __shared__ float sm[];
    float* As = sm;           // 2 bufs * 4*CSA = 8208
    float* Bs = sm + 8208;    // 2 bufs * 4*CSB = 8448

    const int tid = threadIdx.x, lane = tid & 31, warp = tid >> 5;
    const int wm = warp >> 2, wn = warp & 3;
    const int bx = blockIdx.x, by = blockIdx.y;
    const float* Ab = A + (long)by * 128 * DM;
    const float* Wb = W + (long)bx * 128;

    const int a_ch = tid & 3, a_m = tid >> 2;
    const int b_cg = tid & 31, b_k = tid >> 5;

    float acc[4][4][4];
    #pragma unroll
    for (int i = 0; i < 4; i++)
        #pragma unroll
        for (int j = 0; j < 4; j++)
            #pragma unroll
            for (int q = 0; q < 4; q++) acc[i][j][q] = 0.f;

    float4 ar[2][2], br[4];
    const int b_kk = 2 * (b_k & 3) + ((b_k >> 2) & 1);

    #pragma unroll
    for (int p = 0; p < 2; p++) {
        const float* s = Ab + (long)(a_m + 64 * p) * DM + a_ch * 8;
        ar[p][0] = *(const float4*)s;
        ar[p][1] = *(const float4*)(s + 4);
    }
    #pragma unroll
    for (int p = 0; p < 4; p++)
        br[p] = *(const float4*)(Wb + (long)(b_k + 8 * p) * DM + b_cg * 4);

    {
        #pragma unroll
        for (int p = 0; p < 2; p++)
            sts_pair8(As + a_ch * CSA + (a_m + 64 * p) * 8, ar[p][0], ar[p][1]);
        #pragma unroll
        for (int p = 0; p < 4; p++) {
            float* d = Bs + p * CSB + b_kk * RSB + b_cg * 4;
            float4 t;
            t.x = tf(br[p].x); t.y = tf(br[p].y); t.z = tf(br[p].z); t.w = tf(br[p].w);
            *(float4*)d = t;
        }
    }
    __syncthreads();

    const int NK = DM / 32;
    for (int it = 0; it < NK; ++it) {
        const bool pre = (it + 1 < NK);
        if (pre) {
            const int k0 = (it + 1) * 32;
            #pragma unroll
            for (int p = 0; p < 2; p++) {
                const float* s = Ab + (long)(a_m + 64 * p) * DM + k0 + a_ch * 8;
                ar[p][0] = *(const float4*)s;
                ar[p][1] = *(const float4*)(s + 4);
            }
            #pragma unroll
            for (int p = 0; p < 4; p++)
                br[p] = *(const float4*)(Wb + (long)(k0 + b_k + 8 * p) * DM + b_cg * 4);
        }

        const float* Ac = As + (it & 1) * 4104;
        const float* Bc = Bs + (it & 1) * 4224;
        #pragma unroll
        for (int ch = 0; ch < 4; ch++) {
            unsigned a[4][4], b[4][2];
            #pragma unroll
            for (int mi = 0; mi < 4; mi++) {
                int r = wm * 64 + mi * 16 + (lane >> 2);
                float2 lo = *(const float2*)(Ac + ch * CSA + r * 8 + 2 * (lane & 3));
                float2 hi = *(const float2*)(Ac + ch * CSA + (r + 8) * 8 + 2 * (lane & 3));
                a[mi][0] = __float_as_uint(lo.x); a[mi][1] = __float_as_uint(hi.x);
                a[mi][2] = __float_as_uint(lo.y); a[mi][3] = __float_as_uint(hi.y);
            }
            #pragma unroll
            for (int ni = 0; ni < 4; ni++) {
                int n = wn * 32 + ni * 8 + (lane >> 2);
                int c2 = 2 * (lane & 3);
                b[ni][0] = __float_as_uint(Bc[ch * CSB + c2 * RSB + n]);
                b[ni][1] = __float_as_uint(Bc[ch * CSB + (c2 + 1) * RSB + n]);
            }
            #pragma unroll
            for (int mi = 0; mi < 4; mi++)
                #pragma unroll
                for (int ni = 0; ni < 4; ni++)
                    mma_tf32(acc[mi][ni][0], acc[mi][ni][1], acc[mi][ni][2], acc[mi][ni][3],
                             a[mi][0], a[mi][1], a[mi][2], a[mi][3],
                             b[ni][0], b[ni][1]);
        }

        if (pre) {
            float* Ad = As + ((it + 1) & 1) * 4104;
            float* Bd = Bs + ((it + 1) & 1) * 4224;
            #pragma unroll
            for (int p = 0; p < 2; p++)
                sts_pair8(Ad + a_ch * CSA + (a_m + 64 * p) * 8, ar[p][0], ar[p][1]);
            #pragma unroll
            for (int p = 0; p < 4; p++) {
                float* d = Bd + p * CSB + b_kk * RSB + b_cg * 4;
                float4 t;
                t.x = tf(br[p].x); t.y = tf(br[p].y); t.z = tf(br[p].z); t.w = tf(br[p].w);
                *(float4*)d = t;
            }
            __syncthreads();
        }
    }

    #pragma unroll
    for (int mi = 0; mi < 4; mi++) {
        int r0 = by * 128 + wm * 64 + mi * 16 + (lane >> 2);
        #pragma unroll
        for (int ni = 0; ni < 4; ni++) {
            int n = bx * 128 + wn * 32 + ni * 8 + 2 * (lane & 3);
            float bz0 = bias[n], bz1 = bias[n + 1];
            float2 t0, t1;
            t0.x = acc[mi][ni][0] + bz0; t0.y = acc[mi][ni][1] + bz1;
            t1.x = acc[mi][ni][2] + bz0; t1.y = acc[mi][ni][3] + bz1;
            if (SPLIT) {
                int bb = r0 >> 11, s = r0 & 2047;
                int h = n >> 6, d = n & 63;
                long base = (((long)(bb * H_ + h)) * S_ + s) * D_ + d;
                *(float2*)(C + base) = t0;
                *(float2*)(C + base + 8 * D_) = t1;
            } else {
                *(float2*)(C + (long)r0 * DM + n) = t0;
                *(float2*)(C + (long)(r0 + 8) * DM + n) = t1;
            }
        }
    }
}

// ---------------------------------------------------------------------------
// K2: scores -> exp + row sums.
// Per CTA: 128 query rows of one (b,h); sweep 2048 keys in 32 tiles of 64.
// Writes e = exp(score*0.125 + mask) to gmem, inv[row] = 1/sum(e).
// 8 warps 4m x 2n, warp tile 32x32 (acc 32 regs). 2 CTAs/SM.
// Smem: Qs 8208 | Ks 2*4112 | msk 2048 | red 256 = 18736 floats (74.9 KB)
// ---------------------------------------------------------------------------
__global__ __launch_bounds__(256, 2)
void scores_exp_tc(const float* __restrict__ Qh, const float* __restrict__ Kh,
                   const float* __restrict__ mask,
                   float* __restrict__ eout, float* __restrict__ inv_out)
{
    extern __shared__ float sm[];
    float* Qs  = sm;                  // 8208
    float* Ks  = sm + 8208;           // 2 * 4112
    float* msk = sm + 8208 + 8224;    // 2048
    float* red = msk + 2048;          // 256

    const int tid = threadIdx.x, lane = tid & 31, warp = tid >> 5;
    const int wm = warp >> 1, wn = warp & 1;
    const int bh = blockIdx.z;
    const int row0 = blockIdx.x * 128;
    const float* Qb = Qh + ((long)bh * S_ + row0) * D_;
    const float* Kb = Kh + (long)bh * S_ * D_;
    float* eb = eout + (long)bh * S_ * S_ + (long)row0 * S_;
    const int bb = bh >> 4;

    // mask -> smem
    #pragma unroll
    for (int i = tid; i < 512; i += 256)
        ((float4*)msk)[i] = ((const float4*)(mask + (long)bb * S_))[i];

    const int ch = tid & 7, m = tid >> 3;

    // Q (128 rows) -> smem
    #pragma unroll
    for (int p = 0; p < 4; p++) {
        int row = m + 32 * p;
        const float* sq = Qb + (long)row * D_ + ch * 8;
        sts_pair8(Qs + ch * CSA + row * 8, *(const float4*)sq, *(const float4*)(sq + 4));
    }
    // K tile 0 (64 keys) -> buf 0
    #pragma unroll
    for (int p = 0; p < 2; p++) {
        int row = m + 32 * p;
        const float* sk = Kb + (long)row * D_ + ch * 8;
        sts_pair8(Ks + ch * CSA2 + row * 8, *(const float4*)sk, *(const float4*)(sk + 4));
    }
    __syncthreads();

    const int r_w = wm * 32 + (lane >> 2);  // + mi*16, +8
    float ssum[4] = {0.f, 0.f, 0.f, 0.f};
    float4 kr[4];

    const int NT = S_ / 64;   // 32
    for (int kt = 0; kt < NT; ++kt) {
        const bool pre = (kt + 1 < NT);
        if (pre) {
            const int k0 = (kt + 1) * 64;
            #pragma unroll
            for (int p = 0; p < 2; p++) {
                const float* sk = Kb + (long)(k0 + m + 32 * p) * D_ + ch * 8;
                kr[2*p]   = *(const float4*)sk;
                kr[2*p+1] = *(const float4*)(sk + 4);
            }
        }

        float acc[2][4][4];
        #pragma unroll
        for (int i = 0; i < 2; i++)
            #pragma unroll
            for (int j = 0; j < 4; j++)
                #pragma unroll
                for (int q = 0; q < 4; q++) acc[i][j][q] = 0.f;

        const float* Kc = Ks + (kt & 1) * 4112;
        #pragma unroll
        for (int c = 0; c < 8; c++) {
            unsigned a[2][4], b[4][2];
            #pragma unroll
            for (int mi = 0; mi < 2; mi++) {
                int r = r_w + mi * 16;
                float2 lo = *(const float2*)(Qs + c * CSA + r * 8 + 2 * (lane & 3));
                float2 hi = *(const float2*)(Qs + c * CSA + (r + 8) * 8 + 2 * (lane & 3));
                a[mi][0] = __float_as_uint(lo.x); a[mi][1] = __float_as_uint(hi.x);
                a[mi][2] = __float_as_uint(lo.y); a[mi][3] = __float_as_uint(hi.y);
            }
            #pragma unroll
            for (int ni = 0; ni < 4; ni++) {
                int n = wn * 32 + ni * 8 + (lane >> 2);
                float2 v = *(const float2*)(Kc + c * CSA2 + n * 8 + 2 * (lane & 3));
                b[ni][0] = __float_as_uint(v.x);
                b[ni][1] = __float_as_uint(v.y);
            }
            #pragma unroll
            for (int mi = 0; mi < 2; mi++)
                #pragma unroll
                for (int ni = 0; ni < 4; ni++)
                    mma_tf32(acc[mi][ni][0], acc[mi][ni][1], acc[mi][ni][2], acc[mi][ni][3],
                             a[mi][0], a[mi][1], a[mi][2], a[mi][3],
                             b[ni][0], b[ni][1]);
        }

        // epilogue: exp, write, accumulate sums
        #pragma unroll
        for (int mi = 0; mi < 2; mi++) {
            int r = r_w + mi * 16;
            #pragma unroll
            for (int ni = 0; ni < 4; ni++) {
                int n = kt * 64 + wn * 32 + ni * 8 + 2 * (lane & 3);
                float2 mm = *(const float2*)(msk + n);
                float e0 = __expf(fmaf(acc[mi][ni][0], 0.125f, -1e9f * mm.x));
                float e1 = __expf(fmaf(acc[mi][ni][1], 0.125f, -1e9f * mm.y));
                float e2 = __expf(fmaf(acc[mi][ni][2], 0.125f, -1e9f * mm.x));
                float e3 = __expf(fmaf(acc[mi][ni][3], 0.125f, -1e9f * mm.y));
                float2 t0; t0.x = e0; t0.y = e1;
                float2 t1; t1.x = e2; t1.y = e3;
                *(float2*)(eb + (long)r * S_ + n) = t0;
                *(float2*)(eb + (long)(r + 8) * S_ + n) = t1;
                ssum[mi*2]   += e0 + e1;
                ssum[mi*2+1] += e2 + e3;
            }
        }

        if (pre) {
            float* Kd = Ks + ((kt + 1) & 1) * 4112;
            #pragma unroll
            for (int p = 0; p < 2; p++)
                sts_pair8(Kd + ch * CSA2 + (m + 32 * p) * 8, kr[2*p], kr[2*p+1]);
            __syncthreads();
        }
    }

    // reduce: quad lanes, then across the 2 wn warps via smem
    #pragma unroll
    for (int i = 0; i < 4; i++) {
        ssum[i] += __shfl_xor_sync(0xFFFFFFFFu, ssum[i], 1);
        ssum[i] += __shfl_xor_sync(0xFFFFFFFFu, ssum[i], 2);
    }
    if ((lane & 3) == 0) {
        #pragma unroll
        for (int mi = 0; mi < 2; mi++)
            #pragma unroll
            for (int h = 0; h < 2; h++)
                red[wn * 128 + r_w + mi * 16 + 8 * h] = ssum[mi * 2 + h];
    }
    __syncthreads();
    if (tid < 128)
        inv_out[(long)bh * S_ + row0 + tid] = 1.0f / (red[tid] + red[128 + tid]);
}

// ---------------------------------------------------------------------------
// K3: fused normalize + attn write + P@V context.
// Per CTA: 128 rows of one (b,h); 32 tiles of 64 keys.
// Reads exp values, p = e*inv, writes normalized attn in place,
// stages p (tf32) in smem and accumulates ctx = P@V. Warps 4m x 2n.
// ---------------------------------------------------------------------------
__global__ __launch_bounds__(256, 2)
void ctx_attn_tc(float* __restrict__ attn, const float* __restrict__ Vh,
                 const float* __restrict__ inv_in, float* __restrict__ ctx)
{
    extern __shared__ float sm[];
    float* Ps   = sm;                 // 2 * 8208
    float* Vs   = sm + 2 * 8208;      // 2 * 4384
    float* invs = sm + 2 * 8208 + 2 * 4384;  // 128

    const int tid = threadIdx.x, lane = tid & 31, warp = tid >> 5;
    const int wm = warp >> 1, wn = warp & 1;
    const int bh = blockIdx.z;
    const int row0 = blockIdx.x * 128;
    float* rawb = attn + (long)bh * S_ * S_ + (long)row0 * S_;
    const float* Vb = Vh + (long)bh * S_ * D_;

    if (tid < 128) invs[tid] = inv_in[(long)bh * S_ + row0 + tid];
    __syncthreads();

    const int c16 = tid & 15, rl = tid >> 4;   // raw loader
    const int vcg = tid & 15, vk = tid >> 4;   // V loader
    const int pch = c16 >> 1;                  // P chunk for this thread
    const int podd = (c16 & 1);                // pos parity

    float4 rr[8], vr[4];

    // prologue: load tile 0
    #pragma unroll
    for (int p = 0; p < 8; p++) {
        int row = rl + 16 * p;
        rr[p] = *(const float4*)(rawb + (long)row * S_ + c16 * 4);
    }
    #pragma unroll
    for (int p = 0; p < 4; p++)
        vr[p] = *(const float4*)(Vb + (long)(vk + 16 * p) * D_ + vcg * 4);

    // process tile 0 into buf 0
    {
        float* Pd = Ps;
        float* Vd = Vs;
        #pragma unroll
        for (int p = 0; p < 8; p++) {
            int row = rl + 16 * p;
            float iv = invs[row];
            float4 e;
            e.x = rr[p].x * iv;
            e.y = rr[p].y * iv;
            e.z = rr[p].z * iv;
            e.w = rr[p].w * iv;
            *(float4*)(rawb + (long)row * S_ + c16 * 4) = e;
            float ev[4] = {e.x, e.y, e.z, e.w};
            float* d = Pd + pch * CSA + row * 8 + podd;
            #pragma unroll
            for (int j = 0; j < 4; j++) d[2 * j] = tf(ev[j]);
        }
        #pragma unroll
        for (int p = 0; p < 4; p++) {
            int key = vk + 16 * p;
            int chv = key >> 3, kk = 2 * (key & 3) + ((key >> 2) & 1);
            float4 t;
            t.x = tf(vr[p].x); t.y = tf(vr[p].y); t.z = tf(vr[p].z); t.w = tf(vr[p].w);
            *(float4*)(Vd + chv * CSV + kk * RSV + vcg * 4) = t;
        }
    }
    __syncthreads();

    float acc[2][4][4];
    #pragma unroll
    for (int i = 0; i < 2; i++)
        #pragma unroll
        for (int j = 0; j < 4; j++)
            #pragma unroll
            for (int q = 0; q < 4; q++) acc[i][j][q] = 0.f;

    const int NT = S_ / 64;   // 32
    for (int kt = 0; kt < NT; ++kt) {
        const bool pre = (kt + 1 < NT);
        if (pre) {
            const int k0 = (kt + 1) * 64;
            #pragma unroll
            for (int p = 0; p < 8; p++) {
                int row = rl + 16 * p;
                rr[p] = *(const float4*)(rawb + (long)row * S_ + k0 + c16 * 4);
            }
            #pragma unroll
            for (int p = 0; p < 4; p++)
                vr[p] = *(const float4*)(Vb + (long)(k0 + vk + 16 * p) * D_ + vcg * 4);
        }

        const float* Pc = Ps + (kt & 1) * 8208;
        const float* Vc = Vs + (kt & 1) * 4384;
        #pragma unroll
        for (int c = 0; c < 8; c++) {
            unsigned a[2][4], b[4][2];
            #pragma unroll
            for (int mi = 0; mi < 2; mi++) {
                int r = wm * 32 + mi * 16 + (lane >> 2);
                float2 lo = *(const float2*)(Pc + c * CSA + r * 8 + 2 * (lane & 3));
                float2 hi = *(const float2*)(Pc + c * CSA + (r + 8) * 8 + 2 * (lane & 3));
                a[mi][0] = __float_as_uint(lo.x); a[mi][1] = __float_as_uint(hi.x);
                a[mi][2] = __float_as_uint(lo.y); a[mi][3] = __float_as_uint(hi.y);
            }
            #pragma unroll
            for (int ni = 0; ni < 4; ni++) {
                int n = wn * 32 + ni * 8 + (lane >> 2);
                int c2 = 2 * (lane & 3);
                b[ni][0] = __float_as_uint(Vc[c * CSV + c2 * RSV + n]);
                b[ni][1] = __float_as_uint(Vc[c * CSV + (c2 + 1) * RSV + n]);
            }
            #pragma unroll
            for (int mi = 0; mi < 2; mi++)
                #pragma unroll
                for (int ni = 0; ni < 4; ni++)
                    mma_tf32(acc[mi][ni][0], acc[mi][ni][1], acc[mi][ni][2], acc[mi][ni][3],
                             a[mi][0], a[mi][1], a[mi][2], a[mi][3],
                             b[ni][0], b[ni][1]);
        }

        if (pre) {
            const int k0 = (kt + 1) * 64;
            float* Pd = Ps + ((kt + 1) & 1) * 8208;
            float* Vd = Vs + ((kt + 1) & 1) * 4384;
            #pragma unroll
            for (int p = 0; p < 8; p++) {
                int row = rl + 16 * p;
                float iv = invs[row];
                float4 e;
                e.x = rr[p].x * iv;
                e.y = rr[p].y * iv;
                e.z = rr[p].z * iv;
                e.w = rr[p].w * iv;
                *(float4*)(rawb + (long)row * S_ + k0 + c16 * 4) = e;
                float ev[4] = {e.x, e.y, e.z, e.w};
                float* d = Pd + pch * CSA + row * 8 + podd;
                #pragma unroll
                for (int j = 0; j < 4; j++) d[2 * j] = tf(ev[j]);
            }
            #pragma unroll
            for (int p = 0; p < 4; p++) {
                int key = vk + 16 * p;
                int chv = key >> 3, kk = 2 * (key & 3) + ((key >> 2) & 1);
                float4 t;
                t.x = tf(vr[p].x); t.y = tf(vr[p].y); t.z = tf(vr[p].z); t.w = tf(vr[p].w);
                *(float4*)(Vd + chv * CSV + kk * RSV + vcg * 4) = t;
            }
            __syncthreads();
        }
    }

    // epilogue: merged-heads write
    const int bb = bh >> 4, h = bh & 15;
    #pragma unroll
    for (int mi = 0; mi < 2; mi++) {
        int s = row0 + wm * 32 + mi * 16 + (lane >> 2);
        #pragma unroll
        for (int ni = 0; ni < 4; ni++) {
            int d = wn * 32 + ni * 8 + 2 * (lane & 3);
            long base = ((long)bb * S_ + s) * DM + h * 64 + d;
            float2 t0, t1;
            t0.x = acc[mi][ni][0]; t0.y = acc[mi][ni][1];
            t1.x = acc[mi][ni][2]; t1.y = acc[mi][ni][3];
            *(float2*)(ctx + base) = t0;
            *(float2*)(ctx + base + 8 * DM) = t1;
        }
    }
}

// ---------------------------------------------------------------------------
extern "C" void kernel_launch(void* const* d_in, const int* in_sizes, int n_in,
                              void* d_out, int out_size) {
    const float* Q    = (const float*)d_in[0];
    const float* K    = (const float*)d_in[1];
    const float* V    = (const float*)d_in[2];
    const float* mask = (const float*)d_in[3];
    const float* Wq   = (const float*)d_in[4];
    const float* bq   = (const float*)d_in[5];
    const float* Wk   = (const float*)d_in[6];
    const float* bk   = (const float*)d_in[7];
    const float* Wv   = (const float*)d_in[8];
    const float* bv   = (const float*)d_in[9];
    const float* Wo   = (const float*)d_in[10];
    const float* bo   = (const float*)d_in[11];
    float* out = (float*)d_out;

    float *qp, *kp, *vp, *cp, *ap, *ip;
    cudaGetSymbolAddress((void**)&qp, g_q);
    cudaGetSymbolAddress((void**)&kp, g_k);
    cudaGetSymbolAddress((void**)&vp, g_v);
    cudaGetSymbolAddress((void**)&cp, g_ctx);
    cudaGetSymbolAddress((void**)&ap, g_attn);
    cudaGetSymbolAddress((void**)&ip, g_inv);

    float* attn = ((long)out_size >= OUT_ELEMS + ATTN_ELEMS) ? (out + OUT_ELEMS) : ap;

    const int SM_GEMM = (8208 + 8448) * 4;                    // 66624
    const int SM_SCR  = (8208 + 8224 + 2048 + 256) * 4;       // 74944
    const int SM_CTX  = (2 * 8208 + 2 * 4384 + 128) * 4;      // 101248
    cudaFuncSetAttribute(gemm_tc<0>, cudaFuncAttributeMaxDynamicSharedMemorySize, SM_GEMM);
    cudaFuncSetAttribute(gemm_tc<1>, cudaFuncAttributeMaxDynamicSharedMemorySize, SM_GEMM);
    cudaFuncSetAttribute(scores_exp_tc, cudaFuncAttributeMaxDynamicSharedMemorySize, SM_SCR);
    cudaFuncSetAttribute(ctx_attn_tc,   cudaFuncAttributeMaxDynamicSharedMemorySize, SM_CTX);

    dim3 g1(DM / 128, MTOT / 128);
    gemm_tc<1><<<g1, 256, SM_GEMM>>>(Q, Wq, bq, qp);
    gemm_tc<1><<<g1, 256, SM_GEMM>>>(K, Wk, bk, kp);
    gemm_tc<1><<<g1, 256, SM_GEMM>>>(V, Wv, bv, vp);

    dim3 g2(S_ / 128, 1, B_ * H_);
    scores_exp_tc<<<g2, 256, SM_SCR>>>(qp, kp, mask, attn, ip);

    ctx_attn_tc<<<g2, 256, SM_CTX>>>(attn, vp, ip, cp);

    gemm_tc<0><<<g1, 256, SM_GEMM>>>(cp, Wo, bo, out);
}

// round 6
// speedup vs baseline: 1.1399x; 1.0392x over previous
#include <cuda_runtime.h>
#include <cuda_bf16.h>

// Problem constants
#define B_    2
#define H_    16
#define S_    2048
#define D_    64
#define DM    1024
#define MTOT  4096   // B_*S_

static const long OUT_ELEMS  = (long)MTOT * DM;            // 4,194,304
static const long ATTN_ELEMS = (long)B_ * H_ * S_ * S_;    // 134,217,728

// Scratch (device-global; no runtime allocation allowed)
__device__ float g_q[B_*H_*S_*D_];
__device__ float g_k[B_*H_*S_*D_];
__device__ float g_v[B_*H_*S_*D_];
__device__ float g_ctx[MTOT*DM];
__device__ float g_attn[(size_t)B_*H_*S_*S_];
__device__ float g_inv[B_*H_*S_];   // per-row 1/sum(exp)

// ---------------------------------------------------------------------------
// tf32 / mma / ldmatrix helpers
// ---------------------------------------------------------------------------
__device__ __forceinline__ float tf(float f) {
    unsigned u;
    asm("cvt.rna.tf32.f32 %0, %1;" : "=r"(u) : "f"(f));
    return __uint_as_float(u);
}
__device__ __forceinline__ float4 tf4(float4 v) {
    float4 t; t.x = tf(v.x); t.y = tf(v.y); t.z = tf(v.z); t.w = tf(v.w); return t;
}

__device__ __forceinline__ void mma_tf32(
    float& c0, float& c1, float& c2, float& c3,
    unsigned a0, unsigned a1, unsigned a2, unsigned a3,
    unsigned b0, unsigned b1)
{
    asm volatile(
        "mma.sync.aligned.m16n8k8.row.col.f32.tf32.tf32.f32 "
        "{%0,%1,%2,%3},{%4,%5,%6,%7},{%8,%9},{%0,%1,%2,%3};"
        : "+f"(c0), "+f"(c1), "+f"(c2), "+f"(c3)
        : "r"(a0), "r"(a1), "r"(a2), "r"(a3), "r"(b0), "r"(b1));
}

// ldmatrix x4 over fp32 data viewed as b16 pairs: thread i receives float
// [i>>2][i&3] of the 8-row x 4-float tile addressed by its lane group.
__device__ __forceinline__ void ldsm4(unsigned& r0, unsigned& r1,
                                      unsigned& r2, unsigned& r3,
                                      const float* p)
{
    unsigned a = (unsigned)__cvta_generic_to_shared(p);
    asm volatile("ldmatrix.sync.aligned.m8n8.x4.shared.b16 {%0,%1,%2,%3}, [%4];"
                 : "=r"(r0), "=r"(r1), "=r"(r2), "=r"(r3) : "r"(a));
}

// Row-major padded strides (stride%32 == 4 floats -> LDSM conflict-free)
#define ASTR 36    // gemm A tile rows of 32 k-floats + pad
#define QSTR 68    // 64-float rows (Q/K/P) + pad
// gemm W layout (kk-interleaved, scalar LDS)
#define RSB 132
#define CSB 1056
// V tile (d=64) layout: [chunk][kk][68]
#define RSV 68
#define CSV 548

// ---------------------------------------------------------------------------
// K1/K5: C[4096,1024] = A[4096,1024] @ W[1024,1024] + bias   (tf32 MMA)
// A fragments via LDSM from row-major [128][ASTR]; B via scalar LDS (as before)
// ---------------------------------------------------------------------------
template<int SPLIT>
__global__ __launch_bounds__(256)
void gemm_tc(const float* __restrict__ A, const float* __restrict__ W,
             const float* __restrict__ bias, float* __restrict__ C)
{
    extern __shared__ float sm[];
    float* As = sm;           // 2 bufs * 128*ASTR = 9216
    float* Bs = sm + 9216;    // 2 bufs * 4*CSB = 8448

    const int tid = threadIdx.x, lane = tid & 31, warp = tid >> 5;
    const int wm = warp >> 2, wn = warp & 3;
    const int bx = blockIdx.x, by = blockIdx.y;
    const float* Ab = A + (long)by * 128 * DM;
    const float* Wb = W + (long)bx * 128;

    const int a_ch = tid & 3, a_m = tid >> 2;
    const int b_cg = tid & 31, b_k = tid >> 5;

    // LDSM per-thread address components for A
    const int arow = (lane & 7) + ((lane >> 3) & 1) * 8;
    const int acol = ((lane >> 4) & 1) * 4;

    float acc[4][4][4];
    #pragma unroll
    for (int i = 0; i < 4; i++)
        #pragma unroll
        for (int j = 0; j < 4; j++)
            #pragma unroll
            for (int q = 0; q < 4; q++) acc[i][j][q] = 0.f;

    float4 ar[2][2], br[4];
    const int b_kk = 2 * (b_k & 3) + ((b_k >> 2) & 1);

    #pragma unroll
    for (int p = 0; p < 2; p++) {
        const float* s = Ab + (long)(a_m + 64 * p) * DM + a_ch * 8;
        ar[p][0] = *(const float4*)s;
        ar[p][1] = *(const float4*)(s + 4);
    }
    #pragma unroll
    for (int p = 0; p < 4; p++)
        br[p] = *(const float4*)(Wb + (long)(b_k + 8 * p) * DM + b_cg * 4);

    {
        #pragma unroll
        for (int p = 0; p < 2; p++) {
            float* d = As + (a_m + 64 * p) * ASTR + a_ch * 8;
            *(float4*)d = tf4(ar[p][0]);
            *(float4*)(d + 4) = tf4(ar[p][1]);
        }
        #pragma unroll
        for (int p = 0; p < 4; p++)
            *(float4*)(Bs + p * CSB + b_kk * RSB + b_cg * 4) = tf4(br[p]);
    }
    __syncthreads();

    const int NK = DM / 32;
    for (int it = 0; it < NK; ++it) {
        const bool pre = (it + 1 < NK);
        if (pre) {
            const int k0 = (it + 1) * 32;
            #pragma unroll
            for (int p = 0; p < 2; p++) {
                const float* s = Ab + (long)(a_m + 64 * p) * DM + k0 + a_ch * 8;
                ar[p][0] = *(const float4*)s;
                ar[p][1] = *(const float4*)(s + 4);
            }
            #pragma unroll
            for (int p = 0; p < 4; p++)
                br[p] = *(const float4*)(Wb + (long)(k0 + b_k + 8 * p) * DM + b_cg * 4);
        }

        const float* Ac = As + (it & 1) * 4608;
        const float* Bc = Bs + (it & 1) * 4224;
        #pragma unroll
        for (int ch = 0; ch < 4; ch++) {
            unsigned a[4][4], b[4][2];
            #pragma unroll
            for (int mi = 0; mi < 4; mi++)
                ldsm4(a[mi][0], a[mi][1], a[mi][2], a[mi][3],
                      Ac + (wm * 64 + mi * 16 + arow) * ASTR + ch * 8 + acol);
            #pragma unroll
            for (int ni = 0; ni < 4; ni++) {
                int n = wn * 32 + ni * 8 + (lane >> 2);
                int c2 = 2 * (lane & 3);
                b[ni][0] = __float_as_uint(Bc[ch * CSB + c2 * RSB + n]);
                b[ni][1] = __float_as_uint(Bc[ch * CSB + (c2 + 1) * RSB + n]);
            }
            #pragma unroll
            for (int mi = 0; mi < 4; mi++)
                #pragma unroll
                for (int ni = 0; ni < 4; ni++)
                    mma_tf32(acc[mi][ni][0], acc[mi][ni][1], acc[mi][ni][2], acc[mi][ni][3],
                             a[mi][0], a[mi][1], a[mi][2], a[mi][3],
                             b[ni][0], b[ni][1]);
        }

        if (pre) {
            float* Ad = As + ((it + 1) & 1) * 4608;
            float* Bd = Bs + ((it + 1) & 1) * 4224;
            #pragma unroll
            for (int p = 0; p < 2; p++) {
                float* d = Ad + (a_m + 64 * p) * ASTR + a_ch * 8;
                *(float4*)d = tf4(ar[p][0]);
                *(float4*)(d + 4) = tf4(ar[p][1]);
            }
            #pragma unroll
            for (int p = 0; p < 4; p++)
                *(float4*)(Bd + p * CSB + b_kk * RSB + b_cg * 4) = tf4(br[p]);
            __syncthreads();
        }
    }

    #pragma unroll
    for (int mi = 0; mi < 4; mi++) {
        int r0 = by * 128 + wm * 64 + mi * 16 + (lane >> 2);
        #pragma unroll
        for (int ni = 0; ni < 4; ni++) {
            int n = bx * 128 + wn * 32 + ni * 8 + 2 * (lane & 3);
            float bz0 = bias[n], bz1 = bias[n + 1];
            float2 t0, t1;
            t0.x = acc[mi][ni][0] + bz0; t0.y = acc[mi][ni][1] + bz1;
            t1.x = acc[mi][ni][2] + bz0; t1.y = acc[mi][ni][3] + bz1;
            if (SPLIT) {
                int bb = r0 >> 11, s = r0 & 2047;
                int h = n >> 6, d = n & 63;
                long base = (((long)(bb * H_ + h)) * S_ + s) * D_ + d;
                *(float2*)(C + base) = t0;
                *(float2*)(C + base + 8 * D_) = t1;
            } else {
                *(float2*)(C + (long)r0 * DM + n) = t0;
                *(float2*)(C + (long)(r0 + 8) * DM + n) = t1;
            }
        }
    }
}

// ---------------------------------------------------------------------------
// K2: scores -> exp + row sums. Q and K fragments both via LDSM
// (row-major [row][QSTR] tiles). 8 warps 4m x 2n, 2 CTAs/SM.
// ---------------------------------------------------------------------------
__global__ __launch_bounds__(256, 2)
void scores_exp_tc(const float* __restrict__ Qh, const float* __restrict__ Kh,
                   const float* __restrict__ mask,
                   float* __restrict__ eout, float* __restrict__ inv_out)
{
    extern __shared__ float sm[];
    float* Qs  = sm;                    // 128*QSTR = 8704
    float* Ks  = sm + 8704;             // 2 bufs * 64*QSTR = 8704
    float* msk = sm + 8704 + 8704;      // 2048
    float* red = msk + 2048;            // 256

    const int tid = threadIdx.x, lane = tid & 31, warp = tid >> 5;
    const int wm = warp >> 1, wn = warp & 1;
    const int bh = blockIdx.z;
    const int row0 = blockIdx.x * 128;
    const float* Qb = Qh + ((long)bh * S_ + row0) * D_;
    const float* Kb = Kh + (long)bh * S_ * D_;
    float* eb = eout + (long)bh * S_ * S_ + (long)row0 * S_;
    const int bb = bh >> 4;

    #pragma unroll
    for (int i = tid; i < 512; i += 256)
        ((float4*)msk)[i] = ((const float4*)(mask + (long)bb * S_))[i];

    const int ch = tid & 7, m = tid >> 3;

    // Q (128 rows) -> row-major smem
    #pragma unroll
    for (int p = 0; p < 4; p++) {
        int row = m + 32 * p;
        const float* sq = Qb + (long)row * D_ + ch * 8;
        float* d = Qs + row * QSTR + ch * 8;
        *(float4*)d = tf4(*(const float4*)sq);
        *(float4*)(d + 4) = tf4(*(const float4*)(sq + 4));
    }
    // K tile 0 (64 keys)
    #pragma unroll
    for (int p = 0; p < 2; p++) {
        int row = m + 32 * p;
        const float* sk = Kb + (long)row * D_ + ch * 8;
        float* d = Ks + row * QSTR + ch * 8;
        *(float4*)d = tf4(*(const float4*)sk);
        *(float4*)(d + 4) = tf4(*(const float4*)(sk + 4));
    }
    __syncthreads();

    // LDSM addressing
    const int arow = (lane & 7) + ((lane >> 3) & 1) * 8;   // A tiles
    const int acol = ((lane >> 4) & 1) * 4;
    const int brow = (lane & 7) + ((lane >> 4) & 1) * 8;   // B tiles
    const int bcol = ((lane >> 3) & 1) * 4;

    const int r_w = wm * 32 + (lane >> 2);
    float ssum[4] = {0.f, 0.f, 0.f, 0.f};
    float4 kr[4];

    const int NT = S_ / 64;   // 32
    for (int kt = 0; kt < NT; ++kt) {
        const bool pre = (kt + 1 < NT);
        if (pre) {
            const int k0 = (kt + 1) * 64;
            #pragma unroll
            for (int p = 0; p < 2; p++) {
                const float* sk = Kb + (long)(k0 + m + 32 * p) * D_ + ch * 8;
                kr[2*p]   = *(const float4*)sk;
                kr[2*p+1] = *(const float4*)(sk + 4);
            }
        }

        float acc[2][4][4];
        #pragma unroll
        for (int i = 0; i < 2; i++)
            #pragma unroll
            for (int j = 0; j < 4; j++)
                #pragma unroll
                for (int q = 0; q < 4; q++) acc[i][j][q] = 0.f;

        const float* Kc = Ks + (kt & 1) * 4352;
        #pragma unroll
        for (int c = 0; c < 8; c++) {
            unsigned a[2][4], b[4][2];
            #pragma unroll
            for (int mi = 0; mi < 2; mi++)
                ldsm4(a[mi][0], a[mi][1], a[mi][2], a[mi][3],
                      Qs + (wm * 32 + mi * 16 + arow) * QSTR + c * 8 + acol);
            #pragma unroll
            for (int pr = 0; pr < 2; pr++)
                ldsm4(b[2*pr][0], b[2*pr][1], b[2*pr+1][0], b[2*pr+1][1],
                      Kc + (wn * 32 + pr * 16 + brow) * QSTR + c * 8 + bcol);
            #pragma unroll
            for (int mi = 0; mi < 2; mi++)
                #pragma unroll
                for (int ni = 0; ni < 4; ni++)
                    mma_tf32(acc[mi][ni][0], acc[mi][ni][1], acc[mi][ni][2], acc[mi][ni][3],
                             a[mi][0], a[mi][1], a[mi][2], a[mi][3],
                             b[ni][0], b[ni][1]);
        }

        #pragma unroll
        for (int mi = 0; mi < 2; mi++) {
            int r = r_w + mi * 16;
            #pragma unroll
            for (int ni = 0; ni < 4; ni++) {
                int n = kt * 64 + wn * 32 + ni * 8 + 2 * (lane & 3);
                float2 mm = *(const float2*)(msk + n);
                float e0 = __expf(fmaf(acc[mi][ni][0], 0.125f, -1e9f * mm.x));
                float e1 = __expf(fmaf(acc[mi][ni][1], 0.125f, -1e9f * mm.y));
                float e2 = __expf(fmaf(acc[mi][ni][2], 0.125f, -1e9f * mm.x));
                float e3 = __expf(fmaf(acc[mi][ni][3], 0.125f, -1e9f * mm.y));
                float2 t0; t0.x = e0; t0.y = e1;
                float2 t1; t1.x = e2; t1.y = e3;
                *(float2*)(eb + (long)r * S_ + n) = t0;
                *(float2*)(eb + (long)(r + 8) * S_ + n) = t1;
                ssum[mi*2]   += e0 + e1;
                ssum[mi*2+1] += e2 + e3;
            }
        }

        if (pre) {
            float* Kd = Ks + ((kt + 1) & 1) * 4352;
            #pragma unroll
            for (int p = 0; p < 2; p++) {
                float* d = Kd + (m + 32 * p) * QSTR + ch * 8;
                *(float4*)d = tf4(kr[2*p]);
                *(float4*)(d + 4) = tf4(kr[2*p+1]);
            }
            __syncthreads();
        }
    }

    #pragma unroll
    for (int i = 0; i < 4; i++) {
        ssum[i] += __shfl_xor_sync(0xFFFFFFFFu, ssum[i], 1);
        ssum[i] += __shfl_xor_sync(0xFFFFFFFFu, ssum[i], 2);
    }
    if ((lane & 3) == 0) {
        #pragma unroll
        for (int mi = 0; mi < 2; mi++)
            #pragma unroll
            for (int h = 0; h < 2; h++)
                red[wn * 128 + r_w + mi * 16 + 8 * h] = ssum[mi * 2 + h];
    }
    __syncthreads();
    if (tid < 128)
        inv_out[(long)bh * S_ + row0 + tid] = 1.0f / (red[tid] + red[128 + tid]);
}

// ---------------------------------------------------------------------------
// K3: fused normalize + attn write + P@V context. P via LDSM (row-major),
// V via scalar LDS (kk layout). Warps 4m x 2n.
// ---------------------------------------------------------------------------
__global__ __launch_bounds__(256, 2)
void ctx_attn_tc(float* __restrict__ attn, const float* __restrict__ Vh,
                 const float* __restrict__ inv_in, float* __restrict__ ctx)
{
    extern __shared__ float sm[];
    float* Ps   = sm;                 // 2 bufs * 128*QSTR = 17408
    float* Vs   = sm + 17408;         // 2 bufs * 4384
    float* invs = sm + 17408 + 8768;  // 128

    const int tid = threadIdx.x, lane = tid & 31, warp = tid >> 5;
    const int wm = warp >> 1, wn = warp & 1;
    const int bh = blockIdx.z;
    const int row0 = blockIdx.x * 128;
    float* rawb = attn + (long)bh * S_ * S_ + (long)row0 * S_;
    const float* Vb = Vh + (long)bh * S_ * D_;

    if (tid < 128) invs[tid] = inv_in[(long)bh * S_ + row0 + tid];
    __syncthreads();

    const int c16 = tid & 15, rl = tid >> 4;   // raw loader
    const int vcg = tid & 15, vk = tid >> 4;   // V loader

    const int arow = (lane & 7) + ((lane >> 3) & 1) * 8;
    const int acol = ((lane >> 4) & 1) * 4;

    float4 rr[8], vr[4];

    #pragma unroll
    for (int p = 0; p < 8; p++)
        rr[p] = *(const float4*)(rawb + (long)(rl + 16 * p) * S_ + c16 * 4);
    #pragma unroll
    for (int p = 0; p < 4; p++)
        vr[p] = *(const float4*)(Vb + (long)(vk + 16 * p) * D_ + vcg * 4);

    {
        #pragma unroll
        for (int p = 0; p < 8; p++) {
            int row = rl + 16 * p;
            float iv = invs[row];
            float4 e;
            e.x = rr[p].x * iv; e.y = rr[p].y * iv;
            e.z = rr[p].z * iv; e.w = rr[p].w * iv;
            *(float4*)(rawb + (long)row * S_ + c16 * 4) = e;
            *(float4*)(Ps + row * QSTR + c16 * 4) = tf4(e);
        }
        #pragma unroll
        for (int p = 0; p < 4; p++) {
            int key = vk + 16 * p;
            int chv = key >> 3, kk = 2 * (key & 3) + ((key >> 2) & 1);
            *(float4*)(Vs + chv * CSV + kk * RSV + vcg * 4) = tf4(vr[p]);
        }
    }
    __syncthreads();

    float acc[2][4][4];
    #pragma unroll
    for (int i = 0; i < 2; i++)
        #pragma unroll
        for (int j = 0; j < 4; j++)
            #pragma unroll
            for (int q = 0; q < 4; q++) acc[i][j][q] = 0.f;

    const int NT = S_ / 64;   // 32
    for (int kt = 0; kt < NT; ++kt) {
        const bool pre = (kt + 1 < NT);
        if (pre) {
            const int k0 = (kt + 1) * 64;
            #pragma unroll
            for (int p = 0; p < 8; p++)
                rr[p] = *(const float4*)(rawb + (long)(rl + 16 * p) * S_ + k0 + c16 * 4);
            #pragma unroll
            for (int p = 0; p < 4; p++)
                vr[p] = *(const float4*)(Vb + (long)(k0 + vk + 16 * p) * D_ + vcg * 4);
        }

        const float* Pc = Ps + (kt & 1) * 8704;
        const float* Vc = Vs + (kt & 1) * 4384;
        #pragma unroll
        for (int c = 0; c < 8; c++) {
            unsigned a[2][4], b[4][2];
            #pragma unroll
            for (int mi = 0; mi < 2; mi++)
                ldsm4(a[mi][0], a[mi][1], a[mi][2], a[mi][3],
                      Pc + (wm * 32 + mi * 16 + arow) * QSTR + c * 8 + acol);
            #pragma unroll
            for (int ni = 0; ni < 4; ni++) {
                int n = wn * 32 + ni * 8 + (lane >> 2);
                int c2 = 2 * (lane & 3);
                b[ni][0] = __float_as_uint(Vc[c * CSV + c2 * RSV + n]);
                b[ni][1] = __float_as_uint(Vc[c * CSV + (c2 + 1) * RSV + n]);
            }
            #pragma unroll
            for (int mi = 0; mi < 2; mi++)
                #pragma unroll
                for (int ni = 0; ni < 4; ni++)
                    mma_tf32(acc[mi][ni][0], acc[mi][ni][1], acc[mi][ni][2], acc[mi][ni][3],
                             a[mi][0], a[mi][1], a[mi][2], a[mi][3],
                             b[ni][0], b[ni][1]);
        }

        if (pre) {
            const int k0 = (kt + 1) * 64;
            float* Pd = Ps + ((kt + 1) & 1) * 8704;
            float* Vd = Vs + ((kt + 1) & 1) * 4384;
            #pragma unroll
            for (int p = 0; p < 8; p++) {
                int row = rl + 16 * p;
                float iv = invs[row];
                float4 e;
                e.x = rr[p].x * iv; e.y = rr[p].y * iv;
                e.z = rr[p].z * iv; e.w = rr[p].w * iv;
                *(float4*)(rawb + (long)row * S_ + k0 + c16 * 4) = e;
                *(float4*)(Pd + row * QSTR + c16 * 4) = tf4(e);
            }
            #pragma unroll
            for (int p = 0; p < 4; p++) {
                int key = vk + 16 * p;
                int chv = key >> 3, kk = 2 * (key & 3) + ((key >> 2) & 1);
                *(float4*)(Vd + chv * CSV + kk * RSV + vcg * 4) = tf4(vr[p]);
            }
            __syncthreads();
        }
    }

    // epilogue: merged-heads write
    const int bb = bh >> 4, h = bh & 15;
    #pragma unroll
    for (int mi = 0; mi < 2; mi++) {
        int s = row0 + wm * 32 + mi * 16 + (lane >> 2);
        #pragma unroll
        for (int ni = 0; ni < 4; ni++) {
            int d = wn * 32 + ni * 8 + 2 * (lane & 3);
            long base = ((long)bb * S_ + s) * DM + h * 64 + d;
            float2 t0, t1;
            t0.x = acc[mi][ni][0]; t0.y = acc[mi][ni][1];
            t1.x = acc[mi][ni][2]; t1.y = acc[mi][ni][3];
            *(float2*)(ctx + base) = t0;
            *(float2*)(ctx + base + 8 * DM) = t1;
        }
    }
}

// ---------------------------------------------------------------------------
extern "C" void kernel_launch(void* const* d_in, const int* in_sizes, int n_in,
                              void* d_out, int out_size) {
    const float* Q    = (const float*)d_in[0];
    const float* K    = (const float*)d_in[1];
    const float* V    = (const float*)d_in[2];
    const float* mask = (const float*)d_in[3];
    const float* Wq   = (const float*)d_in[4];
    const float* bq   = (const float*)d_in[5];
    const float* Wk   = (const float*)d_in[6];
    const float* bk   = (const float*)d_in[7];
    const float* Wv   = (const float*)d_in[8];
    const float* bv   = (const float*)d_in[9];
    const float* Wo   = (const float*)d_in[10];
    const float* bo   = (const float*)d_in[11];
    float* out = (float*)d_out;

    float *qp, *kp, *vp, *cp, *ap, *ip;
    cudaGetSymbolAddress((void**)&qp, g_q);
    cudaGetSymbolAddress((void**)&kp, g_k);
    cudaGetSymbolAddress((void**)&vp, g_v);
    cudaGetSymbolAddress((void**)&cp, g_ctx);
    cudaGetSymbolAddress((void**)&ap, g_attn);
    cudaGetSymbolAddress((void**)&ip, g_inv);

    float* attn = ((long)out_size >= OUT_ELEMS + ATTN_ELEMS) ? (out + OUT_ELEMS) : ap;

    const int SM_GEMM = (9216 + 8448) * 4;                // 70656
    const int SM_SCR  = (8704 + 8704 + 2048 + 256) * 4;   // 78848
    const int SM_CTX  = (17408 + 8768 + 128) * 4;         // 105216
    cudaFuncSetAttribute(gemm_tc<0>, cudaFuncAttributeMaxDynamicSharedMemorySize, SM_GEMM);
    cudaFuncSetAttribute(gemm_tc<1>, cudaFuncAttributeMaxDynamicSharedMemorySize, SM_GEMM);
    cudaFuncSetAttribute(scores_exp_tc, cudaFuncAttributeMaxDynamicSharedMemorySize, SM_SCR);
    cudaFuncSetAttribute(ctx_attn_tc,   cudaFuncAttributeMaxDynamicSharedMemorySize, SM_CTX);

    dim3 g1(DM / 128, MTOT / 128);
    gemm_tc<1><<<g1, 256, SM_GEMM>>>(Q, Wq, bq, qp);
    gemm_tc<1><<<g1, 256, SM_GEMM>>>(K, Wk, bk, kp);
    gemm_tc<1><<<g1, 256, SM_GEMM>>>(V, Wv, bv, vp);

    dim3 g2(S_ / 128, 1, B_ * H_);
    scores_exp_tc<<<g2, 256, SM_SCR>>>(qp, kp, mask, attn, ip);

    ctx_attn_tc<<<g2, 256, SM_CTX>>>(attn, vp, ip, cp);

    gemm_tc<0><<<g1, 256, SM_GEMM>>>(cp, Wo, bo, out);
}